// round 4
// baseline (speedup 1.0000x reference)
#include <cuda_runtime.h>
#include <cuda_bf16.h>
#include <cuda_fp16.h>
#include <cstdint>

// ---------------- problem constants ----------------
#define NNODES 30000
#define N0     10000
#define NED    400000
#define PROJv  256
#define RREL   6
#define HDS    4
#define C1v    32
#define HC1    128   // H*C1
#define C2v    128
#define LBL    5

// ---------------- device scratch (no runtime allocs allowed) ----------------
__device__ __align__(16) float g_x  [NNODES * PROJv];
__device__ __align__(16) float g_xw [(size_t)RREL * NNODES * 128];
__device__ __align__(16) float g_Qi [(size_t)RREL * NNODES * HDS];
__device__ __align__(16) float g_Kj [(size_t)RREL * NNODES * HDS];
__device__ __align__(16) float g_al [(size_t)NED * HDS];
__device__ __align__(16) float g_h1 [NNODES * HC1];
__device__ __align__(16) float g_h2 [NNODES * C2v];
__device__ __align__(16) float g_wT [RREL * PROJv * HC1];   // transposed weights [r][n][k]
__device__ int g_cnt[NNODES];
__device__ int g_rowptr[NNODES + 1];
__device__ int g_cursor[NNODES];
__device__ int g_perm[NED];

// ---------------- helpers ----------------
__device__ __forceinline__ unsigned packh2(float a, float b) {
    __half2 h = __floats2half2_rn(a, b);
    return *reinterpret_cast<unsigned*>(&h);
}

__device__ __forceinline__ void mma_f16(float* d, const unsigned* a, const unsigned* b) {
    asm volatile(
        "mma.sync.aligned.m16n8k16.row.col.f32.f16.f16.f32 "
        "{%0,%1,%2,%3}, {%4,%5,%6,%7}, {%8,%9}, {%0,%1,%2,%3};\n"
        : "+f"(d[0]), "+f"(d[1]), "+f"(d[2]), "+f"(d[3])
        : "r"(a[0]), "r"(a[1]), "r"(a[2]), "r"(a[3]), "r"(b[0]), "r"(b[1]));
}

// ---------------- FP16 tensor-core GEMM (fp32 in/out, fp32 accum) ----------------
// C[m,n] = sum_k A[m,k] * B[n,k]   (B row-major [N][K], i.e. pre-transposed)
// 128x128x32 CTA tile, 8 warps of 32x64. Inputs converted to fp16 at smem store.
template <bool RELUB>
__global__ __launch_bounds__(256, 2) void hgemm_kernel(
    const float* __restrict__ A, const float* __restrict__ Bm,
    const float* __restrict__ bias, float* __restrict__ C,
    int M, int Nn, int K, long long bStride, long long cStride)
{
    const int STRW = 20;                      // smem row stride in 32-bit words (40 halves)
    __shared__ __align__(16) unsigned As[128 * STRW];
    __shared__ __align__(16) unsigned Bs[128 * STRW];

    const int tid = threadIdx.x;
    const int lane = tid & 31;
    const int wid = tid >> 5;
    const int warp_m = wid & 3;               // 0..3
    const int warp_n = wid >> 2;              // 0..1
    const int bm0 = blockIdx.y * 128;
    const int bn0 = blockIdx.x * 128;
    const float* Bp = Bm + (size_t)blockIdx.z * bStride;
    float* Cp = C + (size_t)blockIdx.z * cStride;

    float acc[2][8][4];
#pragma unroll
    for (int i = 0; i < 2; i++)
#pragma unroll
        for (int j = 0; j < 8; j++)
#pragma unroll
            for (int l = 0; l < 4; l++) acc[i][j][l] = 0.f;

    float4 ra[4], rb[4];
    const float4 z4 = make_float4(0.f, 0.f, 0.f, 0.f);

    auto loadAB = [&](int k0) {
#pragma unroll
        for (int i = 0; i < 4; i++) {
            int f = tid + i * 256;            // 0..1023
            int row = f >> 3;                 // 0..127
            int kq = f & 7;                   // 0..7 -> 4 floats each = 32 K
            int gk = k0 + kq * 4;
            int gm = bm0 + row;
            ra[i] = (gm < M && gk < K) ? *(const float4*)(A + (size_t)gm * K + gk) : z4;
            int gn = bn0 + row;
            rb[i] = (gn < Nn && gk < K) ? *(const float4*)(Bp + (size_t)gn * K + gk) : z4;
        }
    };

    loadAB(0);
    const int niters = (K + 31) >> 5;

    for (int it = 0; it < niters; it++) {
        __syncthreads();
        // convert + store staged tiles as fp16 pairs
#pragma unroll
        for (int i = 0; i < 4; i++) {
            int f = tid + i * 256;
            int row = f >> 3;
            int kq = f & 7;
            uint2 va = make_uint2(packh2(ra[i].x, ra[i].y), packh2(ra[i].z, ra[i].w));
            uint2 vb = make_uint2(packh2(rb[i].x, rb[i].y), packh2(rb[i].z, rb[i].w));
            *(uint2*)&As[row * STRW + kq * 2] = va;
            *(uint2*)&Bs[row * STRW + kq * 2] = vb;
        }
        __syncthreads();
        if (it + 1 < niters) loadAB((it + 1) << 5);

#pragma unroll
        for (int kg = 0; kg < 2; kg++) {      // two k16 groups per 32-K tile
            const int cw = (lane & 3) + kg * 8;   // word offset within row
            unsigned afr[2][4], bfr[8][2];
#pragma unroll
            for (int mt = 0; mt < 2; mt++) {
                int r0 = warp_m * 32 + mt * 16 + (lane >> 2);
                afr[mt][0] = As[r0 * STRW + cw];
                afr[mt][1] = As[(r0 + 8) * STRW + cw];
                afr[mt][2] = As[r0 * STRW + cw + 4];
                afr[mt][3] = As[(r0 + 8) * STRW + cw + 4];
            }
#pragma unroll
            for (int nt = 0; nt < 8; nt++) {
                int n0 = warp_n * 64 + nt * 8 + (lane >> 2);
                bfr[nt][0] = Bs[n0 * STRW + cw];
                bfr[nt][1] = Bs[n0 * STRW + cw + 4];
            }
#pragma unroll
            for (int mt = 0; mt < 2; mt++)
#pragma unroll
                for (int nt = 0; nt < 8; nt++)
                    mma_f16(acc[mt][nt], afr[mt], bfr[nt]);
        }
    }

    // epilogue
#pragma unroll
    for (int mt = 0; mt < 2; mt++) {
        int m0 = bm0 + warp_m * 32 + mt * 16 + (lane >> 2);
#pragma unroll
        for (int nt = 0; nt < 8; nt++) {
            int n = bn0 + warp_n * 64 + nt * 8 + (lane & 3) * 2;
            float b0 = bias ? bias[n] : 0.f;
            float b1 = bias ? bias[n + 1] : 0.f;
            float2 v0 = make_float2(acc[mt][nt][0] + b0, acc[mt][nt][1] + b1);
            float2 v1 = make_float2(acc[mt][nt][2] + b0, acc[mt][nt][3] + b1);
            if (RELUB) {
                v0.x = fmaxf(v0.x, 0.f); v0.y = fmaxf(v0.y, 0.f);
                v1.x = fmaxf(v1.x, 0.f); v1.y = fmaxf(v1.y, 0.f);
            }
            if (m0 < M)     *(float2*)&Cp[(size_t)m0 * Nn + n] = v0;
            if (m0 + 8 < M) *(float2*)&Cp[(size_t)(m0 + 8) * Nn + n] = v1;
        }
    }
}

// ---------------- weight transpose: out[r][n][k] = W[r][k][n] ----------------
__global__ void tr_kernel(const float* __restrict__ W, float* __restrict__ out,
                          int Kd, int Nd, int total)
{
    int idx = blockIdx.x * blockDim.x + threadIdx.x;
    if (idx >= total) return;
    int n = idx % Nd;
    int t = idx / Nd;
    int k = t % Kd;
    int r = t / Kd;
    out[((size_t)r * Nd + n) * Kd + k] = W[idx];
}

// ---------------- per-node attention scalars: Qi/Kj ----------------
template <int H>
__global__ void qk_kernel(const float* __restrict__ xw, const float* __restrict__ q,
                          const float* __restrict__ k, float* __restrict__ Qi,
                          float* __restrict__ Kj, int RN)
{
    int wid = (blockIdx.x * blockDim.x + threadIdx.x) >> 5;
    int lane = threadIdx.x & 31;
    if (wid >= RN) return;
    float4 v = ((const float4*)(xw + (size_t)wid * 128))[lane];
    int c = lane * 4;
#pragma unroll
    for (int h = 0; h < H; h++) {
        float qs = v.x * q[(c + 0) * H + h] + v.y * q[(c + 1) * H + h]
                 + v.z * q[(c + 2) * H + h] + v.w * q[(c + 3) * H + h];
        float ks = v.x * k[(c + 0) * H + h] + v.y * k[(c + 1) * H + h]
                 + v.z * k[(c + 2) * H + h] + v.w * k[(c + 3) * H + h];
#pragma unroll
        for (int o = 16; o; o >>= 1) {
            qs += __shfl_xor_sync(0xffffffffu, qs, o);
            ks += __shfl_xor_sync(0xffffffffu, ks, o);
        }
        if (lane == 0) {
            Qi[(size_t)wid * H + h] = qs;
            Kj[(size_t)wid * H + h] = ks;
        }
    }
}

// ---------------- edge logits ----------------
template <int H>
__global__ void alpha_kernel(const int* __restrict__ src, const int* __restrict__ dst,
                             const int* __restrict__ et, const float* __restrict__ Qi,
                             const float* __restrict__ Kj, float* __restrict__ alpha, int E)
{
    int e = blockIdx.x * blockDim.x + threadIdx.x;
    if (e >= E) return;
    int r = et[e], s = src[e], d = dst[e];
    const float* qd = Qi + ((size_t)r * NNODES + d) * H;
    const float* ks = Kj + ((size_t)r * NNODES + s) * H;
#pragma unroll
    for (int h = 0; h < H; h++) {
        float a = qd[h] + ks[h];
        alpha[(size_t)e * H + h] = (a > 0.f) ? a : 0.2f * a;
    }
}

// ---------------- CSR construction ----------------
__global__ void zero_kernel(int* p, int n)
{
    int i = blockIdx.x * blockDim.x + threadIdx.x;
    if (i < n) p[i] = 0;
}
__global__ void count_kernel(const int* __restrict__ dst, int* __restrict__ cnt, int E)
{
    int e = blockIdx.x * blockDim.x + threadIdx.x;
    if (e < E) atomicAdd(&cnt[dst[e]], 1);
}
__global__ void scan_kernel(const int* __restrict__ cnt, int* __restrict__ rowptr,
                            int* __restrict__ cursor, int n)
{
    __shared__ int sh[1024];
    __shared__ int carry;
    if (threadIdx.x == 0) { carry = 0; rowptr[0] = 0; }
    __syncthreads();
    for (int base = 0; base < n; base += 1024) {
        int i = base + threadIdx.x;
        int v = (i < n) ? cnt[i] : 0;
        sh[threadIdx.x] = v;
        __syncthreads();
        for (int off = 1; off < 1024; off <<= 1) {
            int t = (threadIdx.x >= off) ? sh[threadIdx.x - off] : 0;
            __syncthreads();
            sh[threadIdx.x] += t;
            __syncthreads();
        }
        if (i < n) {
            rowptr[i + 1] = carry + sh[threadIdx.x];
            cursor[i] = carry + sh[threadIdx.x] - v;
        }
        __syncthreads();
        if (threadIdx.x == 0) carry += sh[1023];
        __syncthreads();
    }
}
__global__ void scatter_kernel(const int* __restrict__ dst, int* __restrict__ cursor,
                               int* __restrict__ perm, int E)
{
    int e = blockIdx.x * blockDim.x + threadIdx.x;
    if (e < E) {
        int pos = atomicAdd(&cursor[dst[e]], 1);
        perm[pos] = e;
    }
}

// ---------------- layer 1 softmax + aggregation (H=4, C=32), warp per node ----------------
__global__ void agg1_kernel(const float* __restrict__ xw, const float* __restrict__ alpha,
                            const int* __restrict__ rowptr, const int* __restrict__ perm,
                            const int* __restrict__ src, const int* __restrict__ et,
                            const float* __restrict__ bias, float* __restrict__ out)
{
    int n = (blockIdx.x * blockDim.x + threadIdx.x) >> 5;
    int lane = threadIdx.x & 31;
    if (n >= NNODES) return;
    int beg = rowptr[n], end = rowptr[n + 1];

    float m0 = -1e30f, m1 = -1e30f, m2 = -1e30f, m3 = -1e30f;
    for (int i = beg; i < end; i++) {
        float4 a = ((const float4*)alpha)[perm[i]];
        m0 = fmaxf(m0, a.x); m1 = fmaxf(m1, a.y);
        m2 = fmaxf(m2, a.z); m3 = fmaxf(m3, a.w);
    }
    float s0 = 0.f, s1 = 0.f, s2 = 0.f, s3 = 0.f;
    for (int i = beg; i < end; i++) {
        float4 a = ((const float4*)alpha)[perm[i]];
        s0 += __expf(a.x - m0); s1 += __expf(a.y - m1);
        s2 += __expf(a.z - m2); s3 += __expf(a.w - m3);
    }
    float i0 = 1.f / (s0 + 1e-16f), i1 = 1.f / (s1 + 1e-16f);
    float i2 = 1.f / (s2 + 1e-16f), i3 = 1.f / (s3 + 1e-16f);

    float a0 = 0.f, a1 = 0.f, a2 = 0.f, a3 = 0.f;
    for (int i = beg; i < end; i++) {
        int e = perm[i];
        float4 a = ((const float4*)alpha)[e];
        float w0 = __expf(a.x - m0) * i0;
        float w1 = __expf(a.y - m1) * i1;
        float w2 = __expf(a.z - m2) * i2;
        float w3 = __expf(a.w - m3) * i3;
        const float* base = xw + ((size_t)et[e] * NNODES + src[e]) * 128;
        a0 += w0 * base[lane];
        a1 += w1 * base[32 + lane];
        a2 += w2 * base[64 + lane];
        a3 += w3 * base[96 + lane];
    }
    float* o = out + (size_t)n * 128;
    o[lane]      = fmaxf(a0 + bias[lane], 0.f);
    o[32 + lane] = fmaxf(a1 + bias[32 + lane], 0.f);
    o[64 + lane] = fmaxf(a2 + bias[64 + lane], 0.f);
    o[96 + lane] = fmaxf(a3 + bias[96 + lane], 0.f);
}

// ---------------- layer 2 softmax + aggregation (H=1, C=128), warp per node ----------------
__global__ void agg2_kernel(const float* __restrict__ xw, const float* __restrict__ alpha,
                            const int* __restrict__ rowptr, const int* __restrict__ perm,
                            const int* __restrict__ src, const int* __restrict__ et,
                            const float* __restrict__ bias, float* __restrict__ out)
{
    int n = (blockIdx.x * blockDim.x + threadIdx.x) >> 5;
    int lane = threadIdx.x & 31;
    if (n >= NNODES) return;
    int beg = rowptr[n], end = rowptr[n + 1];

    float m = -1e30f;
    for (int i = beg; i < end; i++) m = fmaxf(m, alpha[perm[i]]);
    float s = 0.f;
    for (int i = beg; i < end; i++) s += __expf(alpha[perm[i]] - m);
    float inv = 1.f / (s + 1e-16f);

    float4 acc = make_float4(0.f, 0.f, 0.f, 0.f);
    for (int i = beg; i < end; i++) {
        int e = perm[i];
        float w = __expf(alpha[e] - m) * inv;
        float4 v = ((const float4*)(xw + ((size_t)et[e] * NNODES + src[e]) * 128))[lane];
        acc.x += w * v.x; acc.y += w * v.y; acc.z += w * v.z; acc.w += w * v.w;
    }
    float4 b = ((const float4*)bias)[lane];
    float4 r;
    r.x = fmaxf(acc.x + b.x, 0.f);
    r.y = fmaxf(acc.y + b.y, 0.f);
    r.z = fmaxf(acc.z + b.z, 0.f);
    r.w = fmaxf(acc.w + b.w, 0.f);
    ((float4*)(out + (size_t)n * 128))[lane] = r;
}

// ---------------- final classifier ----------------
__global__ void cls_kernel(const float* __restrict__ h, const float* __restrict__ Wl,
                           const float* __restrict__ bl, float* __restrict__ out)
{
    int m = (blockIdx.x * blockDim.x + threadIdx.x) >> 5;
    int lane = threadIdx.x & 31;
    if (m >= N0) return;
    float4 v = ((const float4*)(h + (size_t)m * 128))[lane];
#pragma unroll
    for (int j = 0; j < LBL; j++) {
        float4 w = ((const float4*)(Wl + j * 128))[lane];
        float p = v.x * w.x + v.y * w.y + v.z * w.z + v.w * w.w;
#pragma unroll
        for (int o = 16; o; o >>= 1) p += __shfl_xor_sync(0xffffffffu, p, o);
        if (lane == 0) out[(size_t)m * LBL + j] = p + bl[j];
    }
}

// ---------------- launch ----------------
extern "C" void kernel_launch(void* const* d_in, const int* in_sizes, int n_in,
                              void* d_out, int out_size)
{
    const float* x0  = (const float*)d_in[0];
    const float* x1  = (const float*)d_in[1];
    const float* x2  = (const float*)d_in[2];
    const int*   ei  = (const int*)d_in[3];
    const int*   et  = (const int*)d_in[4];
    const float* Wp0 = (const float*)d_in[5];
    const float* bp0 = (const float*)d_in[6];
    const float* Wp1 = (const float*)d_in[7];
    const float* bp1 = (const float*)d_in[8];
    const float* Wp2 = (const float*)d_in[9];
    const float* bp2 = (const float*)d_in[10];
    const float* W1  = (const float*)d_in[11];
    const float* q1  = (const float*)d_in[12];
    const float* k1  = (const float*)d_in[13];
    const float* b1  = (const float*)d_in[14];
    const float* W2  = (const float*)d_in[15];
    const float* q2  = (const float*)d_in[16];
    const float* k2  = (const float*)d_in[17];
    const float* b2  = (const float*)d_in[18];
    const float* Wl  = (const float*)d_in[19];
    const float* bl  = (const float*)d_in[20];

    const int E = in_sizes[4];
    const int* src = ei;
    const int* dst = ei + E;

    float *xb, *xw, *Qi, *Kj, *al, *h1, *h2, *wT;
    int *cnt, *rp, *cur, *pm;
    cudaGetSymbolAddress((void**)&xb, g_x);
    cudaGetSymbolAddress((void**)&xw, g_xw);
    cudaGetSymbolAddress((void**)&Qi, g_Qi);
    cudaGetSymbolAddress((void**)&Kj, g_Kj);
    cudaGetSymbolAddress((void**)&al, g_al);
    cudaGetSymbolAddress((void**)&h1, g_h1);
    cudaGetSymbolAddress((void**)&h2, g_h2);
    cudaGetSymbolAddress((void**)&wT, g_wT);
    cudaGetSymbolAddress((void**)&cnt, g_cnt);
    cudaGetSymbolAddress((void**)&rp, g_rowptr);
    cudaGetSymbolAddress((void**)&cur, g_cursor);
    cudaGetSymbolAddress((void**)&pm, g_perm);

    // --- projections: xb = relu(xi @ Wpi^T + bpi)  (Wp already [N][K]) ---
    hgemm_kernel<true><<<dim3(2, 79, 1), 256>>>(x0, Wp0, bp0, xb,                 N0, PROJv, 2000, 0, 0);
    hgemm_kernel<true><<<dim3(2, 79, 1), 256>>>(x1, Wp1, bp1, xb + N0 * PROJv,    N0, PROJv, 1500, 0, 0);
    hgemm_kernel<true><<<dim3(2, 79, 1), 256>>>(x2, Wp2, bp2, xb + 2 * N0 * PROJv, N0, PROJv, 1000, 0, 0);

    // --- CSR by destination (independent) ---
    zero_kernel<<<(NNODES + 255) / 256, 256>>>(cnt, NNODES);
    count_kernel<<<(E + 255) / 256, 256>>>(dst, cnt, E);
    scan_kernel<<<1, 1024>>>(cnt, rp, cur, NNODES);
    scatter_kernel<<<(E + 255) / 256, 256>>>(dst, cur, pm, E);

    // --- layer 1: xw[r] = xb @ W1[r]  (transpose W1 -> [r][n][k] first) ---
    tr_kernel<<<(RREL * PROJv * HC1 + 255) / 256, 256>>>(W1, wT, PROJv, HC1, RREL * PROJv * HC1);
    hgemm_kernel<false><<<dim3(1, 235, RREL), 256>>>(xb, wT, nullptr, xw,
        NNODES, HC1, PROJv, (long long)PROJv * HC1, (long long)NNODES * HC1);
    {
        int RN = RREL * NNODES;
        qk_kernel<HDS><<<(RN * 32 + 255) / 256, 256>>>(xw, q1, k1, Qi, Kj, RN);
    }
    alpha_kernel<HDS><<<(E + 255) / 256, 256>>>(src, dst, et, Qi, Kj, al, E);
    agg1_kernel<<<(NNODES * 32 + 255) / 256, 256>>>(xw, al, rp, pm, src, et, b1, h1);

    // --- layer 2 ---
    tr_kernel<<<(RREL * HC1 * C2v + 255) / 256, 256>>>(W2, wT, HC1, C2v, RREL * HC1 * C2v);
    hgemm_kernel<false><<<dim3(1, 235, RREL), 256>>>(h1, wT, nullptr, xw,
        NNODES, C2v, HC1, (long long)HC1 * C2v, (long long)NNODES * C2v);
    {
        int RN = RREL * NNODES;
        qk_kernel<1><<<(RN * 32 + 255) / 256, 256>>>(xw, q2, k2, Qi, Kj, RN);
    }
    alpha_kernel<1><<<(E + 255) / 256, 256>>>(src, dst, et, Qi, Kj, al, E);
    agg2_kernel<<<(NNODES * 32 + 255) / 256, 256>>>(xw, al, rp, pm, src, et, b2, h2);

    // --- classifier ---
    cls_kernel<<<(N0 * 32 + 255) / 256, 256>>>(h2, Wl, bl, (float*)d_out);
}

// round 5
// speedup vs baseline: 1.0010x; 1.0010x over previous
#include <cuda_runtime.h>
#include <cuda_bf16.h>
#include <cuda_fp16.h>
#include <cstdint>

// ---------------- problem constants ----------------
#define NNODES 30000
#define N0     10000
#define NED    400000
#define PROJv  256
#define RREL   6
#define HDS    4
#define C1v    32
#define HC1    128   // H*C1
#define C2v    128
#define LBL    5

// ---------------- device scratch (no runtime allocs allowed) ----------------
__device__ __align__(16) float g_x  [NNODES * PROJv];
__device__ __align__(16) float g_xw [(size_t)RREL * NNODES * 128];
__device__ __align__(16) float g_Qi [(size_t)RREL * NNODES * HDS];
__device__ __align__(16) float g_Kj [(size_t)RREL * NNODES * HDS];
__device__ __align__(16) float g_al [(size_t)NED * HDS];
__device__ __align__(16) float g_h1 [NNODES * HC1];
__device__ __align__(16) float g_h2 [NNODES * C2v];
__device__ __align__(16) float g_wT [RREL * PROJv * HC1];   // transposed weights [r][n][k]
__device__ int g_cnt[NNODES];
__device__ int g_rowptr[NNODES + 1];
__device__ int g_cursor[NNODES];
__device__ int g_perm[NED];

// ---------------- helpers ----------------
__device__ __forceinline__ unsigned packh2(float a, float b) {
    __half2 h = __floats2half2_rn(a, b);
    return *reinterpret_cast<unsigned*>(&h);
}

__device__ __forceinline__ void mma_f16(float* d, const unsigned* a, const unsigned* b) {
    asm volatile(
        "mma.sync.aligned.m16n8k16.row.col.f32.f16.f16.f32 "
        "{%0,%1,%2,%3}, {%4,%5,%6,%7}, {%8,%9}, {%0,%1,%2,%3};\n"
        : "+f"(d[0]), "+f"(d[1]), "+f"(d[2]), "+f"(d[3])
        : "r"(a[0]), "r"(a[1]), "r"(a[2]), "r"(a[3]), "r"(b[0]), "r"(b[1]));
}

// ---------------- FP16 tensor-core GEMM (fp32 in/out, fp32 accum) ----------------
// C[m,n] = sum_k A[m,k] * B[n,k]   (B row-major [N][K], i.e. pre-transposed)
// 128x128x32 CTA tile, 8 warps of 32x64. Inputs converted to fp16 at smem store.
template <bool RELUB>
__global__ __launch_bounds__(256, 2) void hgemm_kernel(
    const float* __restrict__ A, const float* __restrict__ Bm,
    const float* __restrict__ bias, float* __restrict__ C,
    int M, int Nn, int K, long long bStride, long long cStride)
{
    const int STRW = 20;                      // smem row stride in 32-bit words (40 halves)
    __shared__ __align__(16) unsigned As[128 * STRW];
    __shared__ __align__(16) unsigned Bs[128 * STRW];

    const int tid = threadIdx.x;
    const int lane = tid & 31;
    const int wid = tid >> 5;
    const int warp_m = wid & 3;               // 0..3
    const int warp_n = wid >> 2;              // 0..1
    const int bm0 = blockIdx.y * 128;
    const int bn0 = blockIdx.x * 128;
    const float* Bp = Bm + (size_t)blockIdx.z * bStride;
    float* Cp = C + (size_t)blockIdx.z * cStride;

    float acc[2][8][4];
#pragma unroll
    for (int i = 0; i < 2; i++)
#pragma unroll
        for (int j = 0; j < 8; j++)
#pragma unroll
            for (int l = 0; l < 4; l++) acc[i][j][l] = 0.f;

    float4 ra[4], rb[4];
    const float4 z4 = make_float4(0.f, 0.f, 0.f, 0.f);

    auto loadAB = [&](int k0) {
#pragma unroll
        for (int i = 0; i < 4; i++) {
            int f = tid + i * 256;            // 0..1023
            int row = f >> 3;                 // 0..127
            int kq = f & 7;                   // 0..7 -> 4 floats each = 32 K
            int gk = k0 + kq * 4;
            int gm = bm0 + row;
            ra[i] = (gm < M && gk < K) ? *(const float4*)(A + (size_t)gm * K + gk) : z4;
            int gn = bn0 + row;
            rb[i] = (gn < Nn && gk < K) ? *(const float4*)(Bp + (size_t)gn * K + gk) : z4;
        }
    };

    loadAB(0);
    const int niters = (K + 31) >> 5;

    for (int it = 0; it < niters; it++) {
        __syncthreads();
        // convert + store staged tiles as fp16 pairs
#pragma unroll
        for (int i = 0; i < 4; i++) {
            int f = tid + i * 256;
            int row = f >> 3;
            int kq = f & 7;
            uint2 va = make_uint2(packh2(ra[i].x, ra[i].y), packh2(ra[i].z, ra[i].w));
            uint2 vb = make_uint2(packh2(rb[i].x, rb[i].y), packh2(rb[i].z, rb[i].w));
            *(uint2*)&As[row * STRW + kq * 2] = va;
            *(uint2*)&Bs[row * STRW + kq * 2] = vb;
        }
        __syncthreads();
        if (it + 1 < niters) loadAB((it + 1) << 5);

#pragma unroll
        for (int kg = 0; kg < 2; kg++) {      // two k16 groups per 32-K tile
            const int cw = (lane & 3) + kg * 8;   // word offset within row
            unsigned afr[2][4], bfr[8][2];
#pragma unroll
            for (int mt = 0; mt < 2; mt++) {
                int r0 = warp_m * 32 + mt * 16 + (lane >> 2);
                afr[mt][0] = As[r0 * STRW + cw];
                afr[mt][1] = As[(r0 + 8) * STRW + cw];
                afr[mt][2] = As[r0 * STRW + cw + 4];
                afr[mt][3] = As[(r0 + 8) * STRW + cw + 4];
            }
#pragma unroll
            for (int nt = 0; nt < 8; nt++) {
                int n0 = warp_n * 64 + nt * 8 + (lane >> 2);
                bfr[nt][0] = Bs[n0 * STRW + cw];
                bfr[nt][1] = Bs[n0 * STRW + cw + 4];
            }
#pragma unroll
            for (int mt = 0; mt < 2; mt++)
#pragma unroll
                for (int nt = 0; nt < 8; nt++)
                    mma_f16(acc[mt][nt], afr[mt], bfr[nt]);
        }
    }

    // epilogue
#pragma unroll
    for (int mt = 0; mt < 2; mt++) {
        int m0 = bm0 + warp_m * 32 + mt * 16 + (lane >> 2);
#pragma unroll
        for (int nt = 0; nt < 8; nt++) {
            int n = bn0 + warp_n * 64 + nt * 8 + (lane & 3) * 2;
            float b0 = bias ? bias[n] : 0.f;
            float b1 = bias ? bias[n + 1] : 0.f;
            float2 v0 = make_float2(acc[mt][nt][0] + b0, acc[mt][nt][1] + b1);
            float2 v1 = make_float2(acc[mt][nt][2] + b0, acc[mt][nt][3] + b1);
            if (RELUB) {
                v0.x = fmaxf(v0.x, 0.f); v0.y = fmaxf(v0.y, 0.f);
                v1.x = fmaxf(v1.x, 0.f); v1.y = fmaxf(v1.y, 0.f);
            }
            if (m0 < M)     *(float2*)&Cp[(size_t)m0 * Nn + n] = v0;
            if (m0 + 8 < M) *(float2*)&Cp[(size_t)(m0 + 8) * Nn + n] = v1;
        }
    }
}

// ---------------- weight transpose: out[r][n][k] = W[r][k][n] ----------------
__global__ void tr_kernel(const float* __restrict__ W, float* __restrict__ out,
                          int Kd, int Nd, int total)
{
    int idx = blockIdx.x * blockDim.x + threadIdx.x;
    if (idx >= total) return;
    int n = idx % Nd;
    int t = idx / Nd;
    int k = t % Kd;
    int r = t / Kd;
    out[((size_t)r * Nd + n) * Kd + k] = W[idx];
}

// ---------------- per-node attention scalars: Qi/Kj ----------------
template <int H>
__global__ void qk_kernel(const float* __restrict__ xw, const float* __restrict__ q,
                          const float* __restrict__ k, float* __restrict__ Qi,
                          float* __restrict__ Kj, int RN)
{
    int wid = (blockIdx.x * blockDim.x + threadIdx.x) >> 5;
    int lane = threadIdx.x & 31;
    if (wid >= RN) return;
    float4 v = ((const float4*)(xw + (size_t)wid * 128))[lane];
    int c = lane * 4;
#pragma unroll
    for (int h = 0; h < H; h++) {
        float qs = v.x * q[(c + 0) * H + h] + v.y * q[(c + 1) * H + h]
                 + v.z * q[(c + 2) * H + h] + v.w * q[(c + 3) * H + h];
        float ks = v.x * k[(c + 0) * H + h] + v.y * k[(c + 1) * H + h]
                 + v.z * k[(c + 2) * H + h] + v.w * k[(c + 3) * H + h];
#pragma unroll
        for (int o = 16; o; o >>= 1) {
            qs += __shfl_xor_sync(0xffffffffu, qs, o);
            ks += __shfl_xor_sync(0xffffffffu, ks, o);
        }
        if (lane == 0) {
            Qi[(size_t)wid * H + h] = qs;
            Kj[(size_t)wid * H + h] = ks;
        }
    }
}

// ---------------- edge logits ----------------
template <int H>
__global__ void alpha_kernel(const int* __restrict__ src, const int* __restrict__ dst,
                             const int* __restrict__ et, const float* __restrict__ Qi,
                             const float* __restrict__ Kj, float* __restrict__ alpha, int E)
{
    int e = blockIdx.x * blockDim.x + threadIdx.x;
    if (e >= E) return;
    int r = et[e], s = src[e], d = dst[e];
    const float* qd = Qi + ((size_t)r * NNODES + d) * H;
    const float* ks = Kj + ((size_t)r * NNODES + s) * H;
#pragma unroll
    for (int h = 0; h < H; h++) {
        float a = qd[h] + ks[h];
        alpha[(size_t)e * H + h] = (a > 0.f) ? a : 0.2f * a;
    }
}

// ---------------- CSR construction ----------------
__global__ void zero_kernel(int* p, int n)
{
    int i = blockIdx.x * blockDim.x + threadIdx.x;
    if (i < n) p[i] = 0;
}
__global__ void count_kernel(const int* __restrict__ dst, int* __restrict__ cnt, int E)
{
    int e = blockIdx.x * blockDim.x + threadIdx.x;
    if (e < E) atomicAdd(&cnt[dst[e]], 1);
}
__global__ void scan_kernel(const int* __restrict__ cnt, int* __restrict__ rowptr,
                            int* __restrict__ cursor, int n)
{
    __shared__ int sh[1024];
    __shared__ int carry;
    if (threadIdx.x == 0) { carry = 0; rowptr[0] = 0; }
    __syncthreads();
    for (int base = 0; base < n; base += 1024) {
        int i = base + threadIdx.x;
        int v = (i < n) ? cnt[i] : 0;
        sh[threadIdx.x] = v;
        __syncthreads();
        for (int off = 1; off < 1024; off <<= 1) {
            int t = (threadIdx.x >= off) ? sh[threadIdx.x - off] : 0;
            __syncthreads();
            sh[threadIdx.x] += t;
            __syncthreads();
        }
        if (i < n) {
            rowptr[i + 1] = carry + sh[threadIdx.x];
            cursor[i] = carry + sh[threadIdx.x] - v;
        }
        __syncthreads();
        if (threadIdx.x == 0) carry += sh[1023];
        __syncthreads();
    }
}
__global__ void scatter_kernel(const int* __restrict__ dst, int* __restrict__ cursor,
                               int* __restrict__ perm, int E)
{
    int e = blockIdx.x * blockDim.x + threadIdx.x;
    if (e < E) {
        int pos = atomicAdd(&cursor[dst[e]], 1);
        perm[pos] = e;
    }
}

// ---------------- layer 1 softmax + aggregation (H=4, C=32), warp per node ----------------
__global__ void agg1_kernel(const float* __restrict__ xw, const float* __restrict__ alpha,
                            const int* __restrict__ rowptr, const int* __restrict__ perm,
                            const int* __restrict__ src, const int* __restrict__ et,
                            const float* __restrict__ bias, float* __restrict__ out)
{
    int n = (blockIdx.x * blockDim.x + threadIdx.x) >> 5;
    int lane = threadIdx.x & 31;
    if (n >= NNODES) return;
    int beg = rowptr[n], end = rowptr[n + 1];

    float m0 = -1e30f, m1 = -1e30f, m2 = -1e30f, m3 = -1e30f;
    for (int i = beg; i < end; i++) {
        float4 a = ((const float4*)alpha)[perm[i]];
        m0 = fmaxf(m0, a.x); m1 = fmaxf(m1, a.y);
        m2 = fmaxf(m2, a.z); m3 = fmaxf(m3, a.w);
    }
    float s0 = 0.f, s1 = 0.f, s2 = 0.f, s3 = 0.f;
    for (int i = beg; i < end; i++) {
        float4 a = ((const float4*)alpha)[perm[i]];
        s0 += __expf(a.x - m0); s1 += __expf(a.y - m1);
        s2 += __expf(a.z - m2); s3 += __expf(a.w - m3);
    }
    float i0 = 1.f / (s0 + 1e-16f), i1 = 1.f / (s1 + 1e-16f);
    float i2 = 1.f / (s2 + 1e-16f), i3 = 1.f / (s3 + 1e-16f);

    float a0 = 0.f, a1 = 0.f, a2 = 0.f, a3 = 0.f;
    for (int i = beg; i < end; i++) {
        int e = perm[i];
        float4 a = ((const float4*)alpha)[e];
        float w0 = __expf(a.x - m0) * i0;
        float w1 = __expf(a.y - m1) * i1;
        float w2 = __expf(a.z - m2) * i2;
        float w3 = __expf(a.w - m3) * i3;
        const float* base = xw + ((size_t)et[e] * NNODES + src[e]) * 128;
        a0 += w0 * base[lane];
        a1 += w1 * base[32 + lane];
        a2 += w2 * base[64 + lane];
        a3 += w3 * base[96 + lane];
    }
    float* o = out + (size_t)n * 128;
    o[lane]      = fmaxf(a0 + bias[lane], 0.f);
    o[32 + lane] = fmaxf(a1 + bias[32 + lane], 0.f);
    o[64 + lane] = fmaxf(a2 + bias[64 + lane], 0.f);
    o[96 + lane] = fmaxf(a3 + bias[96 + lane], 0.f);
}

// ---------------- layer 2 softmax + aggregation (H=1, C=128), warp per node ----------------
__global__ void agg2_kernel(const float* __restrict__ xw, const float* __restrict__ alpha,
                            const int* __restrict__ rowptr, const int* __restrict__ perm,
                            const int* __restrict__ src, const int* __restrict__ et,
                            const float* __restrict__ bias, float* __restrict__ out)
{
    int n = (blockIdx.x * blockDim.x + threadIdx.x) >> 5;
    int lane = threadIdx.x & 31;
    if (n >= NNODES) return;
    int beg = rowptr[n], end = rowptr[n + 1];

    float m = -1e30f;
    for (int i = beg; i < end; i++) m = fmaxf(m, alpha[perm[i]]);
    float s = 0.f;
    for (int i = beg; i < end; i++) s += __expf(alpha[perm[i]] - m);
    float inv = 1.f / (s + 1e-16f);

    float4 acc = make_float4(0.f, 0.f, 0.f, 0.f);
    for (int i = beg; i < end; i++) {
        int e = perm[i];
        float w = __expf(alpha[e] - m) * inv;
        float4 v = ((const float4*)(xw + ((size_t)et[e] * NNODES + src[e]) * 128))[lane];
        acc.x += w * v.x; acc.y += w * v.y; acc.z += w * v.z; acc.w += w * v.w;
    }
    float4 b = ((const float4*)bias)[lane];
    float4 r;
    r.x = fmaxf(acc.x + b.x, 0.f);
    r.y = fmaxf(acc.y + b.y, 0.f);
    r.z = fmaxf(acc.z + b.z, 0.f);
    r.w = fmaxf(acc.w + b.w, 0.f);
    ((float4*)(out + (size_t)n * 128))[lane] = r;
}

// ---------------- final classifier ----------------
__global__ void cls_kernel(const float* __restrict__ h, const float* __restrict__ Wl,
                           const float* __restrict__ bl, float* __restrict__ out)
{
    int m = (blockIdx.x * blockDim.x + threadIdx.x) >> 5;
    int lane = threadIdx.x & 31;
    if (m >= N0) return;
    float4 v = ((const float4*)(h + (size_t)m * 128))[lane];
#pragma unroll
    for (int j = 0; j < LBL; j++) {
        float4 w = ((const float4*)(Wl + j * 128))[lane];
        float p = v.x * w.x + v.y * w.y + v.z * w.z + v.w * w.w;
#pragma unroll
        for (int o = 16; o; o >>= 1) p += __shfl_xor_sync(0xffffffffu, p, o);
        if (lane == 0) out[(size_t)m * LBL + j] = p + bl[j];
    }
}

// ---------------- launch ----------------
extern "C" void kernel_launch(void* const* d_in, const int* in_sizes, int n_in,
                              void* d_out, int out_size)
{
    const float* x0  = (const float*)d_in[0];
    const float* x1  = (const float*)d_in[1];
    const float* x2  = (const float*)d_in[2];
    const int*   ei  = (const int*)d_in[3];
    const int*   et  = (const int*)d_in[4];
    const float* Wp0 = (const float*)d_in[5];
    const float* bp0 = (const float*)d_in[6];
    const float* Wp1 = (const float*)d_in[7];
    const float* bp1 = (const float*)d_in[8];
    const float* Wp2 = (const float*)d_in[9];
    const float* bp2 = (const float*)d_in[10];
    const float* W1  = (const float*)d_in[11];
    const float* q1  = (const float*)d_in[12];
    const float* k1  = (const float*)d_in[13];
    const float* b1  = (const float*)d_in[14];
    const float* W2  = (const float*)d_in[15];
    const float* q2  = (const float*)d_in[16];
    const float* k2  = (const float*)d_in[17];
    const float* b2  = (const float*)d_in[18];
    const float* Wl  = (const float*)d_in[19];
    const float* bl  = (const float*)d_in[20];

    const int E = in_sizes[4];
    const int* src = ei;
    const int* dst = ei + E;

    float *xb, *xw, *Qi, *Kj, *al, *h1, *h2, *wT;
    int *cnt, *rp, *cur, *pm;
    cudaGetSymbolAddress((void**)&xb, g_x);
    cudaGetSymbolAddress((void**)&xw, g_xw);
    cudaGetSymbolAddress((void**)&Qi, g_Qi);
    cudaGetSymbolAddress((void**)&Kj, g_Kj);
    cudaGetSymbolAddress((void**)&al, g_al);
    cudaGetSymbolAddress((void**)&h1, g_h1);
    cudaGetSymbolAddress((void**)&h2, g_h2);
    cudaGetSymbolAddress((void**)&wT, g_wT);
    cudaGetSymbolAddress((void**)&cnt, g_cnt);
    cudaGetSymbolAddress((void**)&rp, g_rowptr);
    cudaGetSymbolAddress((void**)&cur, g_cursor);
    cudaGetSymbolAddress((void**)&pm, g_perm);

    // --- projections: xb = relu(xi @ Wpi^T + bpi)  (Wp already [N][K]) ---
    hgemm_kernel<true><<<dim3(2, 79, 1), 256>>>(x0, Wp0, bp0, xb,                 N0, PROJv, 2000, 0, 0);
    hgemm_kernel<true><<<dim3(2, 79, 1), 256>>>(x1, Wp1, bp1, xb + N0 * PROJv,    N0, PROJv, 1500, 0, 0);
    hgemm_kernel<true><<<dim3(2, 79, 1), 256>>>(x2, Wp2, bp2, xb + 2 * N0 * PROJv, N0, PROJv, 1000, 0, 0);

    // --- CSR by destination (independent) ---
    zero_kernel<<<(NNODES + 255) / 256, 256>>>(cnt, NNODES);
    count_kernel<<<(E + 255) / 256, 256>>>(dst, cnt, E);
    scan_kernel<<<1, 1024>>>(cnt, rp, cur, NNODES);
    scatter_kernel<<<(E + 255) / 256, 256>>>(dst, cur, pm, E);

    // --- layer 1: xw[r] = xb @ W1[r]  (transpose W1 -> [r][n][k] first) ---
    tr_kernel<<<(RREL * PROJv * HC1 + 255) / 256, 256>>>(W1, wT, PROJv, HC1, RREL * PROJv * HC1);
    hgemm_kernel<false><<<dim3(1, 235, RREL), 256>>>(xb, wT, nullptr, xw,
        NNODES, HC1, PROJv, (long long)PROJv * HC1, (long long)NNODES * HC1);
    {
        int RN = RREL * NNODES;
        qk_kernel<HDS><<<(RN * 32 + 255) / 256, 256>>>(xw, q1, k1, Qi, Kj, RN);
    }
    alpha_kernel<HDS><<<(E + 255) / 256, 256>>>(src, dst, et, Qi, Kj, al, E);
    agg1_kernel<<<(NNODES * 32 + 255) / 256, 256>>>(xw, al, rp, pm, src, et, b1, h1);

    // --- layer 2 ---
    tr_kernel<<<(RREL * HC1 * C2v + 255) / 256, 256>>>(W2, wT, HC1, C2v, RREL * HC1 * C2v);
    hgemm_kernel<false><<<dim3(1, 235, RREL), 256>>>(h1, wT, nullptr, xw,
        NNODES, C2v, HC1, (long long)HC1 * C2v, (long long)NNODES * C2v);
    {
        int RN = RREL * NNODES;
        qk_kernel<1><<<(RN * 32 + 255) / 256, 256>>>(xw, q2, k2, Qi, Kj, RN);
    }
    alpha_kernel<1><<<(E + 255) / 256, 256>>>(src, dst, et, Qi, Kj, al, E);
    agg2_kernel<<<(NNODES * 32 + 255) / 256, 256>>>(xw, al, rp, pm, src, et, b2, h2);

    // --- classifier ---
    cls_kernel<<<(N0 * 32 + 255) / 256, 256>>>(h2, Wl, bl, (float*)d_out);
}